// round 12
// baseline (speedup 1.0000x reference)
#include <cuda_runtime.h>
#include <math.h>

#define BB 512
#define LL 196
#define CC 64
#define C2 128
#define CHN 128
#define NEC 512
#define NXC 15

// ---- output layout (flattened tuple order) ----
#define REC_N    (BB*CHN*LL)
#define PRED_OFF (REC_N)
#define LOSS_OFF (REC_N + BB*LL)
#define Q_OFF    (LOSS_OFF + 3)

#define NTHR 416        // 13 warps
#define QSLOT 104       // row slots per code-quarter (4*104 = 416)

// ---- scratch ----
__device__ float  g_q4[BB*LL*CC];
__device__ float  g_E5T[NXC*NEC*CC];
__device__ float  g_EHT[4*NXC*NEC*C2];
__device__ float  g_e2_5[NXC*NEC];
__device__ float  g_e2_h[4*NXC*NEC];
__device__ double g_acc[6];

// packed f32x2 fma: bit-identical to two scalar __fmaf_rn
__device__ __forceinline__ void ffma2(unsigned long long& acc,
                                      unsigned long long a,
                                      unsigned long long b) {
    asm("fma.rn.f32x2 %0, %1, %2, %0;" : "+l"(acc) : "l"(a), "l"(b));
}
__device__ __forceinline__ unsigned long long pack2(float x) {
    unsigned long long r;
    asm("mov.b64 %0, {%1, %1};" : "=l"(r) : "r"(__float_as_uint(x)));
    return r;
}

// [D][N] -> [N][D] transpose per codebook; which 0 -> g_E5T, 1 -> g_EHT
// (also zeroes g_acc from its first block)
__global__ void transpose_k(const float* __restrict__ src, int D, int N, int which) {
    __shared__ float tile[32][33];
    if (which == 0 && blockIdx.x == 0 && blockIdx.y == 0 && blockIdx.z == 0 &&
        threadIdx.y == 0 && threadIdx.x < 6)
        g_acc[threadIdx.x] = 0.0;
    float* dstbase = which ? g_EHT : g_E5T;
    const float* s = src + (size_t)blockIdx.z * D * N;
    float* d = dstbase + (size_t)blockIdx.z * D * N;
    int n0 = blockIdx.x * 32, d0 = blockIdx.y * 32;
    for (int ty = threadIdx.y; ty < 32; ty += 8)
        tile[ty][threadIdx.x] = s[(size_t)(d0 + ty) * N + n0 + threadIdx.x];
    __syncthreads();
    for (int ty = threadIdx.y; ty < 32; ty += 8)
        d[(size_t)(n0 + ty) * D + d0 + threadIdx.x] = tile[threadIdx.x][ty];
}

// e2 for BOTH tables in one launch. XLA column-reduce style (bit-identical).
__global__ void e2_all_k() {
    int n = blockIdx.x * (blockDim.x >> 5) + (threadIdx.x >> 5);
    int lane = threadIdx.x & 31;
    const int T5 = NXC * NEC;
    const int TH = 4 * NXC * NEC;
    if (n >= T5 + TH) return;
    const float* row;
    float* dst;
    int D;
    if (n < T5) { row = g_E5T + (size_t)n * CC;        dst = g_e2_5 + n;        D = CC; }
    else        { row = g_EHT + (size_t)(n - T5) * C2; dst = g_e2_h + (n - T5); D = C2; }
    float p = 0.f;
    for (int j = lane; j < D; j += 32)
        p = __fadd_rn(p, __fmul_rn(row[j], row[j]));
    #pragma unroll
    for (int o = 16; o; o >>= 1)
        p = __fadd_rn(p, __shfl_down_sync(0xffffffffu, p, o));
    if (lane == 0) *dst = p;
}

template<int NW>
__device__ __forceinline__ float block_reduceNW(float v, float* red) {
    #pragma unroll
    for (int o = 16; o; o >>= 1) v += __shfl_down_sync(0xffffffffu, v, o);
    int w = threadIdx.x >> 5;
    if ((threadIdx.x & 31) == 0) red[w] = v;
    __syncthreads();
    float s = 0.f;
    if (threadIdx.x == 0) {
        #pragma unroll
        for (int i = 0; i < NW; ++i) s += red[i];
    }
    return s;
}

// ---- VQ: one block per (b [, level]), full 196 rows x 512 codes.
// 416 threads = 4 code-quarters (32 codes each, tile = 128 codes, 4 tiles)
// x 104 row slots; each slot owns rows slot and slot+104.
// Per warp per k: 10 LDS wavefronts vs 32 FFMA2 (16 fma-cyc) -> fma-bound.
template<int KD, bool HI>
__global__ __launch_bounds__(NTHR, 1)
void vq_kernel(const float* __restrict__ enc,
               const float* __restrict__ Ebase,
               const int*   __restrict__ label,
               float*       __restrict__ qout_hi)
{
    constexpr int PL = 197;                   // 197 mod 32 = 5 -> conflict-free
    extern __shared__ float sm[];
    float* Xst = sm;                          // KD*PL
    float* x2s = Xst + KD * PL;               // 196
    float* Es  = x2s + 196;                   // KD*128 (offset mult of 4 floats)
    float* e2a = Es + KD * 128;               // 512 (all e2, preloaded)
    float* bv  = e2a + 512;                   // 2*416
    int*   bn  = (int*)(bv + 2 * NTHR);       // 2*416
    int*   bestn = bn + 2 * NTHR;             // 196
    float* red = (float*)(bestn + LL);        // 13

    const int b = blockIdx.x;
    const int lev = HI ? blockIdx.y : 0;
    const int cb = label[b];
    const int tid = threadIdx.x;
    const int qtr = tid / QSLOT;              // 0..3, owns codes qtr*32..qtr*32+31
    const int slot = tid - qtr * QSLOT;       // row A = slot
    const bool hasB = (slot < LL - QSLOT);    // row B = slot + 104 (92 valid)
    const int rowB = hasB ? slot + QSLOT : slot;

    const float* X  = HI ? (enc + (size_t)(3 - lev) * (BB * LL * CC)) : enc;
    const float* Eg = Ebase + ((size_t)(HI ? lev * NXC : 0) + cb) * ((size_t)KD * NEC);
    const float* ET = (HI ? g_EHT : g_E5T) + ((size_t)(HI ? lev * NXC : 0) + cb) * ((size_t)NEC * KD);
    const float* e2 = (HI ? g_e2_h : g_e2_5) + ((size_t)(HI ? lev * NXC : 0) + cb) * NEC;
    float* qout = HI ? (qout_hi + (size_t)lev * (BB * LL * C2)) : g_q4;
    double* acc = g_acc + (HI ? 1 + lev : 0);

    // stage X transposed: Xst[d][l]
    for (int idx = tid; idx < LL * KD; idx += NTHR) {
        int ll = idx / KD, d = idx % KD;
        float v;
        if (HI) v = (d < CC) ? X[((size_t)b * LL + ll) * CC + d]
                             : g_q4[((size_t)b * LL + ll) * CC + (d - CC)];
        else    v = X[((size_t)b * LL + ll) * CC + d];
        Xst[d * PL + ll] = v;
    }
    // preload ALL e2 (same values -> bit-identical dists)
    for (int i = tid; i < NEC; i += NTHR) e2a[i] = e2[i];
    __syncthreads();

    // x2 per row — XLA row-reduce (lane-strided unfused + shfl tree)
    {
        const int warp = tid >> 5, lane = tid & 31;
        for (int r = warp; r < LL; r += 13) {
            float p = 0.f;
            #pragma unroll
            for (int j = 0; j < KD / 32; ++j) {
                float xv = Xst[(lane + 32 * j) * PL + r];
                p = __fadd_rn(p, __fmul_rn(xv, xv));
            }
            #pragma unroll
            for (int o = 16; o; o >>= 1)
                p = __fadd_rn(p, __shfl_down_sync(0xffffffffu, p, o));
            if (lane == 0) x2s[r] = p;
        }
    }
    __syncthreads();

    const float x2A = x2s[slot];
    const float x2B = x2s[rowB];
    float bestA = 3.402823466e38f, bestB = 3.402823466e38f;
    int biA = 0x7fffffff, biB = 0x7fffffff;

    for (int t = 0; t < NEC / 128; ++t) {     // 4 tiles of 128 codes
        __syncthreads();
        // stage E tile [KD][128] (n-contiguous rows -> coalesced float4)
        for (int i = tid; i < KD * 32; i += NTHR) {
            int k = i >> 5, j = i & 31;
            ((float4*)Es)[k * 32 + j] = *(const float4*)(Eg + (size_t)k * NEC + t * 128 + j * 4);
        }
        __syncthreads();

        unsigned long long aA[16], aB[16];
        #pragma unroll
        for (int m = 0; m < 16; ++m) { aA[m] = 0ull; aB[m] = 0ull; }
        #pragma unroll 4
        for (int k = 0; k < KD; ++k) {
            unsigned long long xxA = pack2(Xst[k * PL + slot]);
            unsigned long long xxB = pack2(Xst[k * PL + rowB]);
            const ulonglong2* er = (const ulonglong2*)(Es + k * 128 + qtr * 32);
            #pragma unroll
            for (int j = 0; j < 8; ++j) {
                ulonglong2 e = er[j];
                ffma2(aA[2 * j],     xxA, e.x);
                ffma2(aA[2 * j + 1], xxA, e.y);
                ffma2(aB[2 * j],     xxB, e.x);
                ffma2(aB[2 * j + 1], xxB, e.y);
            }
        }
        #pragma unroll
        for (int m = 0; m < 16; ++m) {
            int n0 = t * 128 + qtr * 32 + 2 * m;
            float e0 = e2a[n0], e1 = e2a[n0 + 1];
            float dA0 = __fadd_rn(__fsub_rn(x2A, __fmul_rn(2.f, __uint_as_float((unsigned)aA[m]))), e0);
            float dA1 = __fadd_rn(__fsub_rn(x2A, __fmul_rn(2.f, __uint_as_float((unsigned)(aA[m] >> 32)))), e1);
            float dB0 = __fadd_rn(__fsub_rn(x2B, __fmul_rn(2.f, __uint_as_float((unsigned)aB[m]))), e0);
            float dB1 = __fadd_rn(__fsub_rn(x2B, __fmul_rn(2.f, __uint_as_float((unsigned)(aB[m] >> 32)))), e1);
            if (dA0 < bestA) { bestA = dA0; biA = n0; }
            if (dA1 < bestA) { bestA = dA1; biA = n0 + 1; }
            if (dB0 < bestB) { bestB = dB0; biB = n0; }
            if (dB1 < bestB) { bestB = dB1; biB = n0 + 1; }
        }
    }
    bv[tid] = bestA; bn[tid] = biA;
    bv[NTHR + tid] = bestB; bn[NTHR + tid] = biB;   // only slots<92 entries are read
    __syncthreads();

    // combine 4 quarters per row: global first-min (smallest index among equal minima)
    if (tid < LL) {
        int base = (tid < QSLOT) ? tid : (NTHR + tid - QSLOT);
        float v = bv[base]; int n = bn[base];
        #pragma unroll
        for (int q = 1; q < 4; ++q) {
            float vq = bv[base + q * QSLOT]; int nq = bn[base + q * QSLOT];
            if (vq < v || (vq == v && nq < n)) { v = vq; n = nq; }
        }
        bestn[tid] = n;
    }
    __syncthreads();

    // gather codes, straight-through q, diff
    float lsum = 0.f;
    for (int idx = tid; idx < LL * KD; idx += NTHR) {
        int ll = idx / KD, d = idx % KD;
        float c  = ET[(size_t)bestn[ll] * KD + d];
        float xv = Xst[d * PL + ll];
        float df = __fsub_rn(c, xv);
        lsum = __fmaf_rn(df, df, lsum);
        qout[((size_t)b * LL + ll) * KD + d] = __fadd_rn(xv, df);
    }
    float bs = block_reduceNW<13>(lsum, red);
    if (tid == 0) atomicAdd(acc, (double)bs);
}

// ---- projection + pred + feature loss (unchanged passing version) ----
__global__ __launch_bounds__(NTHR, 1)
void proj_kernel(const float* __restrict__ dec,
                 const float* __restrict__ org,
                 const float* __restrict__ W,
                 const float* __restrict__ bvec,
                 const int*   __restrict__ label,
                 float*       __restrict__ rec_out,
                 float*       __restrict__ pred_out)
{
    constexpr int PL = 197;
    extern __shared__ float sm[];
    float* Dst = sm;                // 128*PL
    float* ps  = Dst + 128 * PL;    // 208
    float* Ws  = ps + 208;          // 128*64
    float* red = Ws + 128 * 64;     // 13

    const int b = blockIdx.x, tid = threadIdx.x;
    const int cb = label[b];
    const int half = (tid >= 208) ? 1 : 0;
    const int l = tid - 208 * half;

    for (int idx = tid; idx < LL * CHN; idx += NTHR) {
        int ll = idx >> 7, d = idx & 127;
        Dst[d * PL + ll] = dec[((size_t)ll * BB + b) * CHN + d];
    }
    const float* Wcb = W + (size_t)cb * CHN * CHN;
    const float* bcb = bvec + cb * CHN;
    float psum = 0.f;

    for (int t = 0; t < 2; ++t) {
        __syncthreads();
        for (int i = tid; i < 128 * 16; i += NTHR) {
            int k = i >> 4, j = i & 15;
            ((float4*)Ws)[k * 16 + j] = *(const float4*)(Wcb + (size_t)k * CHN + t * 64 + j * 4);
        }
        __syncthreads();
        if (l < LL) {
            unsigned long long a2[16];
            #pragma unroll
            for (int j = 0; j < 16; ++j) a2[j] = 0ull;
            #pragma unroll 2
            for (int k = 0; k < 128; ++k) {
                unsigned long long xx = pack2(Dst[k * PL + l]);
                const ulonglong2* er = (const ulonglong2*)(Ws + k * 64 + half * 32);
                #pragma unroll
                for (int j = 0; j < 8; ++j) {
                    ulonglong2 e = er[j];
                    ffma2(a2[2 * j], xx, e.x);
                    ffma2(a2[2 * j + 1], xx, e.y);
                }
            }
            #pragma unroll
            for (int j = 0; j < 16; ++j) {
                #pragma unroll
                for (int ss = 0; ss < 2; ++ss) {
                    float av = __uint_as_float((unsigned)(a2[j] >> (32 * ss)));
                    int o = t * 64 + half * 32 + 2 * j + ss;
                    float r = __fadd_rn(av, bcb[o]);
                    float g = org[(size_t)b * CHN * LL + (size_t)o * LL + l];
                    float e = __fsub_rn(r, g);
                    psum = __fmaf_rn(e, e, psum);
                    rec_out[(size_t)b * CHN * LL + (size_t)o * LL + l] = r;
                }
            }
        }
    }
    __syncthreads();
    if (half == 1 && l < LL) ps[l] = psum;
    __syncthreads();
    if (half == 0 && l < LL)
        pred_out[(size_t)b * LL + l] = __fsqrt_rn(__fadd_rn(psum, ps[l]));
    float bs = block_reduceNW<13>(psum, red);
    if (tid == 0) atomicAdd(&g_acc[5], (double)bs);
}

__global__ void final_k(float* __restrict__ out) {
    if (threadIdx.x == 0 && blockIdx.x == 0) {
        double latent = g_acc[0] / ((double)BB * LL * CC)
                      + (g_acc[1] + g_acc[2] + g_acc[3] + g_acc[4]) / ((double)BB * LL * C2);
        double feat = g_acc[5] / ((double)BB * CHN * LL);
        out[LOSS_OFF + 0] = (float)(0.25 * latent + feat);
        out[LOSS_OFF + 1] = (float)feat;
        out[LOSS_OFF + 2] = (float)latent;
    }
}

extern "C" void kernel_launch(void* const* d_in, const int* in_sizes, int n_in,
                              void* d_out, int out_size) {
    const float* enc      = (const float*)d_in[0];
    const float* dec      = (const float*)d_in[1];
    const float* org      = (const float*)d_in[2];
    const float* embed5   = (const float*)d_in[3];
    const float* embed_hi = (const float*)d_in[4];
    const float* W        = (const float*)d_in[5];
    const float* bvec     = (const float*)d_in[6];
    const int*   label    = (const int*)d_in[7];
    float* out = (float*)d_out;

    // floats: Xst(KD*197)+x2s(196)+Es(KD*128)+e2a(512)+bv(832)+bn(832)+bestn(196)+red(13)+pad
    const size_t sm64  = (size_t)(64  * 197 + 196 + 64  * 128 + 512 + 2 * NTHR + 2 * NTHR + LL + 13 + 16) * 4;
    const size_t sm128 = (size_t)(128 * 197 + 196 + 128 * 128 + 512 + 2 * NTHR + 2 * NTHR + LL + 13 + 16) * 4;
    const size_t smP   = (size_t)(128 * 197 + 208 + 128 * 64 + 13 + 16) * 4;

    cudaFuncSetAttribute((const void*)vq_kernel<64, false>,
                         cudaFuncAttributeMaxDynamicSharedMemorySize, (int)sm64);
    cudaFuncSetAttribute((const void*)vq_kernel<128, true>,
                         cudaFuncAttributeMaxDynamicSharedMemorySize, (int)sm128);
    cudaFuncSetAttribute((const void*)proj_kernel,
                         cudaFuncAttributeMaxDynamicSharedMemorySize, (int)smP);

    // launch order: profiled slot = 0-based launch 3 = vq5
    transpose_k<<<dim3(16, 2, 15), dim3(32, 8)>>>(embed5,   64,  512, 0);   // 0 (zeroes g_acc)
    transpose_k<<<dim3(16, 4, 60), dim3(32, 8)>>>(embed_hi, 128, 512, 1);   // 1
    e2_all_k<<<(75 * 512 + 7) / 8, 256>>>();                                // 2

    vq_kernel<64, false><<<512, NTHR, sm64>>>(                              // 3 <- profiled
        enc + (size_t)4 * BB * LL * CC, embed5, label, nullptr);
    vq_kernel<128, true><<<dim3(512, 4), NTHR, sm128>>>(                    // 4
        enc, embed_hi, label, out + Q_OFF);

    proj_kernel<<<512, NTHR, smP>>>(dec, org, W, bvec, label, out, out + PRED_OFF);  // 5

    final_k<<<1, 1>>>(out);                                                 // 6
}

// round 13
// speedup vs baseline: 1.0842x; 1.0842x over previous
#include <cuda_runtime.h>
#include <math.h>

#define BB 512
#define LL 196
#define CC 64
#define C2 128
#define CHN 128
#define NEC 512
#define NXC 15

// ---- output layout (flattened tuple order) ----
#define REC_N    (BB*CHN*LL)
#define PRED_OFF (REC_N)
#define LOSS_OFF (REC_N + BB*LL)
#define Q_OFF    (LOSS_OFF + 3)

#define NTHR 416        // vq5/proj: 13 warps
#define QSLOT 104       // vq5: row slots per code-quarter (4*104)
#define HTHR 224        // vq_hi: 7 warps, occ 2
#define HSLOT 56        // vq_hi: row slots per code-quarter (4*56)
#define HROWS 98        // vq_hi rows per block (196 = 2*98)

// ---- scratch ----
__device__ float  g_q4[BB*LL*CC];
__device__ float  g_E5T[NXC*NEC*CC];
__device__ float  g_EHT[4*NXC*NEC*C2];
__device__ float  g_e2_5[NXC*NEC];
__device__ float  g_e2_h[4*NXC*NEC];
__device__ double g_acc[6];

// packed f32x2 fma: bit-identical to two scalar __fmaf_rn
__device__ __forceinline__ void ffma2(unsigned long long& acc,
                                      unsigned long long a,
                                      unsigned long long b) {
    asm("fma.rn.f32x2 %0, %1, %2, %0;" : "+l"(acc) : "l"(a), "l"(b));
}
__device__ __forceinline__ unsigned long long pack2(float x) {
    unsigned long long r;
    asm("mov.b64 %0, {%1, %1};" : "=l"(r) : "r"(__float_as_uint(x)));
    return r;
}

// [D][N] -> [N][D] transpose per codebook; which 0 -> g_E5T, 1 -> g_EHT
// (also zeroes g_acc from its first block)
__global__ void transpose_k(const float* __restrict__ src, int D, int N, int which) {
    __shared__ float tile[32][33];
    if (which == 0 && blockIdx.x == 0 && blockIdx.y == 0 && blockIdx.z == 0 &&
        threadIdx.y == 0 && threadIdx.x < 6)
        g_acc[threadIdx.x] = 0.0;
    float* dstbase = which ? g_EHT : g_E5T;
    const float* s = src + (size_t)blockIdx.z * D * N;
    float* d = dstbase + (size_t)blockIdx.z * D * N;
    int n0 = blockIdx.x * 32, d0 = blockIdx.y * 32;
    for (int ty = threadIdx.y; ty < 32; ty += 8)
        tile[ty][threadIdx.x] = s[(size_t)(d0 + ty) * N + n0 + threadIdx.x];
    __syncthreads();
    for (int ty = threadIdx.y; ty < 32; ty += 8)
        d[(size_t)(n0 + ty) * D + d0 + threadIdx.x] = tile[threadIdx.x][ty];
}

// e2 for BOTH tables in one launch. XLA column-reduce style (bit-identical).
__global__ void e2_all_k() {
    int n = blockIdx.x * (blockDim.x >> 5) + (threadIdx.x >> 5);
    int lane = threadIdx.x & 31;
    const int T5 = NXC * NEC;
    const int TH = 4 * NXC * NEC;
    if (n >= T5 + TH) return;
    const float* row;
    float* dst;
    int D;
    if (n < T5) { row = g_E5T + (size_t)n * CC;        dst = g_e2_5 + n;        D = CC; }
    else        { row = g_EHT + (size_t)(n - T5) * C2; dst = g_e2_h + (n - T5); D = C2; }
    float p = 0.f;
    for (int j = lane; j < D; j += 32)
        p = __fadd_rn(p, __fmul_rn(row[j], row[j]));
    #pragma unroll
    for (int o = 16; o; o >>= 1)
        p = __fadd_rn(p, __shfl_down_sync(0xffffffffu, p, o));
    if (lane == 0) *dst = p;
}

template<int NW>
__device__ __forceinline__ float block_reduceNW(float v, float* red) {
    #pragma unroll
    for (int o = 16; o; o >>= 1) v += __shfl_down_sync(0xffffffffu, v, o);
    int w = threadIdx.x >> 5;
    if ((threadIdx.x & 31) == 0) red[w] = v;
    __syncthreads();
    float s = 0.f;
    if (threadIdx.x == 0) {
        #pragma unroll
        for (int i = 0; i < NW; ++i) s += red[i];
    }
    return s;
}

// ---- vq5 (R11 config, unchanged): one block per b, 196 rows x 512 codes,
// 416 threads = 4 quarters (16 codes) x 104 slots, rows slot & slot+104, occ 2.
__global__ __launch_bounds__(NTHR, 2)
void vq5_kernel(const float* __restrict__ enc,
                const float* __restrict__ Ebase,
                const int*   __restrict__ label,
                float*       __restrict__ unused)
{
    constexpr int KD = CC;
    constexpr int PL = 197;
    extern __shared__ float sm[];
    float* Xst = sm;                          // KD*PL
    float* x2s = Xst + KD * PL;               // 196
    float* Es  = x2s + 196;                   // KD*64
    float* e2a = Es + KD * 64;                // 512
    float* bv  = e2a + 512;                   // 2*416
    int*   bn  = (int*)(bv + 2 * NTHR);       // 2*416
    int*   bestn = bn + 2 * NTHR;             // 196
    float* red = (float*)(bestn + LL);        // 13

    const int b = blockIdx.x;
    const int cb = label[b];
    const int tid = threadIdx.x;
    const int qtr = tid / QSLOT;
    const int slot = tid - qtr * QSLOT;
    const bool hasB = (slot < LL - QSLOT);
    const int rowB = hasB ? slot + QSLOT : slot;

    const float* X  = enc;
    const float* Eg = Ebase + (size_t)cb * ((size_t)KD * NEC);
    const float* ET = g_E5T + (size_t)cb * ((size_t)NEC * KD);
    const float* e2 = g_e2_5 + (size_t)cb * NEC;

    for (int idx = tid; idx < LL * KD; idx += NTHR) {
        int ll = idx / KD, d = idx % KD;
        Xst[d * PL + ll] = X[((size_t)b * LL + ll) * CC + d];
    }
    for (int i = tid; i < NEC; i += NTHR) e2a[i] = e2[i];
    __syncthreads();

    {
        const int warp = tid >> 5, lane = tid & 31;
        for (int r = warp; r < LL; r += 13) {
            float p = 0.f;
            #pragma unroll
            for (int j = 0; j < KD / 32; ++j) {
                float xv = Xst[(lane + 32 * j) * PL + r];
                p = __fadd_rn(p, __fmul_rn(xv, xv));
            }
            #pragma unroll
            for (int o = 16; o; o >>= 1)
                p = __fadd_rn(p, __shfl_down_sync(0xffffffffu, p, o));
            if (lane == 0) x2s[r] = p;
        }
    }
    __syncthreads();

    const float x2A = x2s[slot];
    const float x2B = x2s[rowB];
    float bestA = 3.402823466e38f, bestB = 3.402823466e38f;
    int biA = 0x7fffffff, biB = 0x7fffffff;

    for (int t = 0; t < NEC / 64; ++t) {
        __syncthreads();
        for (int i = tid; i < KD * 16; i += NTHR) {
            int k = i >> 4, j = i & 15;
            ((float4*)Es)[k * 16 + j] = *(const float4*)(Eg + (size_t)k * NEC + t * 64 + j * 4);
        }
        __syncthreads();

        unsigned long long aA[8], aB[8];
        #pragma unroll
        for (int m = 0; m < 8; ++m) { aA[m] = 0ull; aB[m] = 0ull; }
        #pragma unroll 4
        for (int k = 0; k < KD; ++k) {
            unsigned long long xxA = pack2(Xst[k * PL + slot]);
            unsigned long long xxB = pack2(Xst[k * PL + rowB]);
            const ulonglong2* er = (const ulonglong2*)(Es + k * 64 + qtr * 16);
            #pragma unroll
            for (int j = 0; j < 4; ++j) {
                ulonglong2 e = er[j];
                ffma2(aA[2 * j],     xxA, e.x);
                ffma2(aA[2 * j + 1], xxA, e.y);
                ffma2(aB[2 * j],     xxB, e.x);
                ffma2(aB[2 * j + 1], xxB, e.y);
            }
        }
        #pragma unroll
        for (int m = 0; m < 8; ++m) {
            int n0 = t * 64 + qtr * 16 + 2 * m;
            float e0 = e2a[n0], e1 = e2a[n0 + 1];
            float dA0 = __fadd_rn(__fsub_rn(x2A, __fmul_rn(2.f, __uint_as_float((unsigned)aA[m]))), e0);
            float dA1 = __fadd_rn(__fsub_rn(x2A, __fmul_rn(2.f, __uint_as_float((unsigned)(aA[m] >> 32)))), e1);
            float dB0 = __fadd_rn(__fsub_rn(x2B, __fmul_rn(2.f, __uint_as_float((unsigned)aB[m]))), e0);
            float dB1 = __fadd_rn(__fsub_rn(x2B, __fmul_rn(2.f, __uint_as_float((unsigned)(aB[m] >> 32)))), e1);
            if (dA0 < bestA) { bestA = dA0; biA = n0; }
            if (dA1 < bestA) { bestA = dA1; biA = n0 + 1; }
            if (dB0 < bestB) { bestB = dB0; biB = n0; }
            if (dB1 < bestB) { bestB = dB1; biB = n0 + 1; }
        }
    }
    bv[tid] = bestA; bn[tid] = biA;
    bv[NTHR + tid] = bestB; bn[NTHR + tid] = biB;
    __syncthreads();

    if (tid < LL) {
        int base = (tid < QSLOT) ? tid : (NTHR + tid - QSLOT);
        float v = bv[base]; int n = bn[base];
        #pragma unroll
        for (int q = 1; q < 4; ++q) {
            float vq = bv[base + q * QSLOT]; int nq = bn[base + q * QSLOT];
            if (vq < v || (vq == v && nq < n)) { v = vq; n = nq; }
        }
        bestn[tid] = n;
    }
    __syncthreads();

    float lsum = 0.f;
    for (int idx = tid; idx < LL * KD; idx += NTHR) {
        int ll = idx / KD, d = idx % KD;
        float c  = ET[(size_t)bestn[ll] * KD + d];
        float xv = Xst[d * PL + ll];
        float df = __fsub_rn(c, xv);
        lsum = __fmaf_rn(df, df, lsum);
        g_q4[((size_t)b * LL + ll) * KD + d] = __fadd_rn(xv, df);
    }
    float bs = block_reduceNW<13>(lsum, red);
    if (tid == 0) atomicAdd(&g_acc[0], (double)bs);
}

// ---- vq_hi: grid (B, 4 levels, 2 row-halves); 98 rows x 512 codes per block.
// 224 threads = 4 quarters (16 codes) x 56 slots; slot owns rows slot & slot+56
// (42 valid B). smem ~88KB -> occupancy 2: two blocks' barriers decouple.
__global__ __launch_bounds__(HTHR, 2)
void vq_hi_kernel(const float* __restrict__ enc,
                  const float* __restrict__ Ebase,
                  const int*   __restrict__ label,
                  float*       __restrict__ qout_hi)
{
    constexpr int KD = C2;
    constexpr int PL = 99;                    // odd: conflict-free column access
    extern __shared__ float sm[];
    float* Xst = sm;                          // KD*PL = 12672
    float* x2s = Xst + KD * PL;               // 98 (+2 pad -> Es 16B aligned)
    float* Es  = x2s + 100;                   // KD*64
    float* e2a = Es + KD * 64;                // 512
    float* bv  = e2a + 512;                   // 2*224
    int*   bn  = (int*)(bv + 2 * HTHR);       // 2*224
    int*   bestn = bn + 2 * HTHR;             // 98
    float* red = (float*)(bestn + HROWS);     // 7

    const int b = blockIdx.x;
    const int lev = blockIdx.y;
    const int row0 = blockIdx.z * HROWS;
    const int cb = label[b];
    const int tid = threadIdx.x;
    const int qtr = tid / HSLOT;              // 0..3
    const int slot = tid - qtr * HSLOT;       // 0..55; row A = slot (<98 always)
    const bool hasB = (slot < HROWS - HSLOT); // 42 valid
    const int rowB = hasB ? slot + HSLOT : slot;

    const float* X  = enc + (size_t)(3 - lev) * (BB * LL * CC);
    const float* Eg = Ebase + ((size_t)lev * NXC + cb) * ((size_t)KD * NEC);
    const float* ET = g_EHT + ((size_t)lev * NXC + cb) * ((size_t)NEC * KD);
    const float* e2 = g_e2_h + ((size_t)lev * NXC + cb) * NEC;
    float* qout = qout_hi + (size_t)lev * (BB * LL * C2);
    double* acc = g_acc + 1 + lev;

    // stage this block's 98 rows transposed: Xst[d][l]
    for (int idx = tid; idx < HROWS * KD; idx += HTHR) {
        int ll = idx / KD, d = idx % KD;
        int gl = row0 + ll;
        float v = (d < CC) ? X[((size_t)b * LL + gl) * CC + d]
                           : g_q4[((size_t)b * LL + gl) * CC + (d - CC)];
        Xst[d * PL + ll] = v;
    }
    for (int i = tid; i < NEC; i += HTHR) e2a[i] = e2[i];
    __syncthreads();

    // x2 — XLA row-reduce (lane-strided unfused + shfl tree), 7 warps
    {
        const int warp = tid >> 5, lane = tid & 31;
        for (int r = warp; r < HROWS; r += 7) {
            float p = 0.f;
            #pragma unroll
            for (int j = 0; j < KD / 32; ++j) {
                float xv = Xst[(lane + 32 * j) * PL + r];
                p = __fadd_rn(p, __fmul_rn(xv, xv));
            }
            #pragma unroll
            for (int o = 16; o; o >>= 1)
                p = __fadd_rn(p, __shfl_down_sync(0xffffffffu, p, o));
            if (lane == 0) x2s[r] = p;
        }
    }
    __syncthreads();

    const float x2A = x2s[slot];
    const float x2B = x2s[rowB];
    float bestA = 3.402823466e38f, bestB = 3.402823466e38f;
    int biA = 0x7fffffff, biB = 0x7fffffff;

    for (int t = 0; t < NEC / 64; ++t) {
        __syncthreads();
        for (int i = tid; i < KD * 16; i += HTHR) {
            int k = i >> 4, j = i & 15;
            ((float4*)Es)[k * 16 + j] = *(const float4*)(Eg + (size_t)k * NEC + t * 64 + j * 4);
        }
        __syncthreads();

        unsigned long long aA[8], aB[8];
        #pragma unroll
        for (int m = 0; m < 8; ++m) { aA[m] = 0ull; aB[m] = 0ull; }
        #pragma unroll 4
        for (int k = 0; k < KD; ++k) {
            unsigned long long xxA = pack2(Xst[k * PL + slot]);
            unsigned long long xxB = pack2(Xst[k * PL + rowB]);
            const ulonglong2* er = (const ulonglong2*)(Es + k * 64 + qtr * 16);
            #pragma unroll
            for (int j = 0; j < 4; ++j) {
                ulonglong2 e = er[j];
                ffma2(aA[2 * j],     xxA, e.x);
                ffma2(aA[2 * j + 1], xxA, e.y);
                ffma2(aB[2 * j],     xxB, e.x);
                ffma2(aB[2 * j + 1], xxB, e.y);
            }
        }
        #pragma unroll
        for (int m = 0; m < 8; ++m) {
            int n0 = t * 64 + qtr * 16 + 2 * m;
            float e0 = e2a[n0], e1 = e2a[n0 + 1];
            float dA0 = __fadd_rn(__fsub_rn(x2A, __fmul_rn(2.f, __uint_as_float((unsigned)aA[m]))), e0);
            float dA1 = __fadd_rn(__fsub_rn(x2A, __fmul_rn(2.f, __uint_as_float((unsigned)(aA[m] >> 32)))), e1);
            float dB0 = __fadd_rn(__fsub_rn(x2B, __fmul_rn(2.f, __uint_as_float((unsigned)aB[m]))), e0);
            float dB1 = __fadd_rn(__fsub_rn(x2B, __fmul_rn(2.f, __uint_as_float((unsigned)(aB[m] >> 32)))), e1);
            if (dA0 < bestA) { bestA = dA0; biA = n0; }
            if (dA1 < bestA) { bestA = dA1; biA = n0 + 1; }
            if (dB0 < bestB) { bestB = dB0; biB = n0; }
            if (dB1 < bestB) { bestB = dB1; biB = n0 + 1; }
        }
    }
    bv[tid] = bestA; bn[tid] = biA;
    bv[HTHR + tid] = bestB; bn[HTHR + tid] = biB;   // only hasB entries are read
    __syncthreads();

    // combine 4 quarters per row: global first-min
    if (tid < HROWS) {
        int base = (tid < HSLOT) ? tid : (HTHR + tid - HSLOT);
        float v = bv[base]; int n = bn[base];
        #pragma unroll
        for (int q = 1; q < 4; ++q) {
            float vq = bv[base + q * HSLOT]; int nq = bn[base + q * HSLOT];
            if (vq < v || (vq == v && nq < n)) { v = vq; n = nq; }
        }
        bestn[tid] = n;
    }
    __syncthreads();

    // gather codes, straight-through q, diff (this block's 98 rows)
    float lsum = 0.f;
    for (int idx = tid; idx < HROWS * KD; idx += HTHR) {
        int ll = idx / KD, d = idx % KD;
        float c  = ET[(size_t)bestn[ll] * KD + d];
        float xv = Xst[d * PL + ll];
        float df = __fsub_rn(c, xv);
        lsum = __fmaf_rn(df, df, lsum);
        qout[((size_t)b * LL + row0 + ll) * KD + d] = __fadd_rn(xv, df);
    }
    float bs = block_reduceNW<7>(lsum, red);
    if (tid == 0) atomicAdd(acc, (double)bs);
}

// ---- projection + pred + feature loss (unchanged passing version) ----
__global__ __launch_bounds__(NTHR, 1)
void proj_kernel(const float* __restrict__ dec,
                 const float* __restrict__ org,
                 const float* __restrict__ W,
                 const float* __restrict__ bvec,
                 const int*   __restrict__ label,
                 float*       __restrict__ rec_out,
                 float*       __restrict__ pred_out)
{
    constexpr int PL = 197;
    extern __shared__ float sm[];
    float* Dst = sm;                // 128*PL
    float* ps  = Dst + 128 * PL;    // 208
    float* Ws  = ps + 208;          // 128*64
    float* red = Ws + 128 * 64;     // 13

    const int b = blockIdx.x, tid = threadIdx.x;
    const int cb = label[b];
    const int half = (tid >= 208) ? 1 : 0;
    const int l = tid - 208 * half;

    for (int idx = tid; idx < LL * CHN; idx += NTHR) {
        int ll = idx >> 7, d = idx & 127;
        Dst[d * PL + ll] = dec[((size_t)ll * BB + b) * CHN + d];
    }
    const float* Wcb = W + (size_t)cb * CHN * CHN;
    const float* bcb = bvec + cb * CHN;
    float psum = 0.f;

    for (int t = 0; t < 2; ++t) {
        __syncthreads();
        for (int i = tid; i < 128 * 16; i += NTHR) {
            int k = i >> 4, j = i & 15;
            ((float4*)Ws)[k * 16 + j] = *(const float4*)(Wcb + (size_t)k * CHN + t * 64 + j * 4);
        }
        __syncthreads();
        if (l < LL) {
            unsigned long long a2[16];
            #pragma unroll
            for (int j = 0; j < 16; ++j) a2[j] = 0ull;
            #pragma unroll 2
            for (int k = 0; k < 128; ++k) {
                unsigned long long xx = pack2(Dst[k * PL + l]);
                const ulonglong2* er = (const ulonglong2*)(Ws + k * 64 + half * 32);
                #pragma unroll
                for (int j = 0; j < 8; ++j) {
                    ulonglong2 e = er[j];
                    ffma2(a2[2 * j], xx, e.x);
                    ffma2(a2[2 * j + 1], xx, e.y);
                }
            }
            #pragma unroll
            for (int j = 0; j < 16; ++j) {
                #pragma unroll
                for (int ss = 0; ss < 2; ++ss) {
                    float av = __uint_as_float((unsigned)(a2[j] >> (32 * ss)));
                    int o = t * 64 + half * 32 + 2 * j + ss;
                    float r = __fadd_rn(av, bcb[o]);
                    float g = org[(size_t)b * CHN * LL + (size_t)o * LL + l];
                    float e = __fsub_rn(r, g);
                    psum = __fmaf_rn(e, e, psum);
                    rec_out[(size_t)b * CHN * LL + (size_t)o * LL + l] = r;
                }
            }
        }
    }
    __syncthreads();
    if (half == 1 && l < LL) ps[l] = psum;
    __syncthreads();
    if (half == 0 && l < LL)
        pred_out[(size_t)b * LL + l] = __fsqrt_rn(__fadd_rn(psum, ps[l]));
    float bs = block_reduceNW<13>(psum, red);
    if (tid == 0) atomicAdd(&g_acc[5], (double)bs);
}

__global__ void final_k(float* __restrict__ out) {
    if (threadIdx.x == 0 && blockIdx.x == 0) {
        double latent = g_acc[0] / ((double)BB * LL * CC)
                      + (g_acc[1] + g_acc[2] + g_acc[3] + g_acc[4]) / ((double)BB * LL * C2);
        double feat = g_acc[5] / ((double)BB * CHN * LL);
        out[LOSS_OFF + 0] = (float)(0.25 * latent + feat);
        out[LOSS_OFF + 1] = (float)feat;
        out[LOSS_OFF + 2] = (float)latent;
    }
}

extern "C" void kernel_launch(void* const* d_in, const int* in_sizes, int n_in,
                              void* d_out, int out_size) {
    const float* enc      = (const float*)d_in[0];
    const float* dec      = (const float*)d_in[1];
    const float* org      = (const float*)d_in[2];
    const float* embed5   = (const float*)d_in[3];
    const float* embed_hi = (const float*)d_in[4];
    const float* W        = (const float*)d_in[5];
    const float* bvec     = (const float*)d_in[6];
    const int*   label    = (const int*)d_in[7];
    float* out = (float*)d_out;

    // vq5 floats: Xst(64*197)+x2s(196)+Es(64*64)+e2a(512)+bv(832)+bn(832)+bestn(196)+red(13)
    const size_t sm5 = (size_t)(64 * 197 + 196 + 64 * 64 + 512 + 2 * NTHR + 2 * NTHR + LL + 13 + 16) * 4;
    // vq_hi floats: Xst(128*99)+pad(100)+Es(128*64)+e2a(512)+bv(448)+bn(448)+bestn(98)+red(7)
    const size_t smH = (size_t)(128 * 99 + 100 + 128 * 64 + 512 + 2 * HTHR + 2 * HTHR + HROWS + 7 + 16) * 4;
    const size_t smP = (size_t)(128 * 197 + 208 + 128 * 64 + 13 + 16) * 4;

    cudaFuncSetAttribute((const void*)vq5_kernel,
                         cudaFuncAttributeMaxDynamicSharedMemorySize, (int)sm5);
    cudaFuncSetAttribute((const void*)vq_hi_kernel,
                         cudaFuncAttributeMaxDynamicSharedMemorySize, (int)smH);
    cudaFuncSetAttribute((const void*)proj_kernel,
                         cudaFuncAttributeMaxDynamicSharedMemorySize, (int)smP);

    // launch order: profiled slot = 0-based launch 3 = vq5
    transpose_k<<<dim3(16, 2, 15), dim3(32, 8)>>>(embed5,   64,  512, 0);   // 0 (zeroes g_acc)
    transpose_k<<<dim3(16, 4, 60), dim3(32, 8)>>>(embed_hi, 128, 512, 1);   // 1
    e2_all_k<<<(75 * 512 + 7) / 8, 256>>>();                                // 2

    vq5_kernel<<<512, NTHR, sm5>>>(                                         // 3 <- profiled
        enc + (size_t)4 * BB * LL * CC, embed5, label, nullptr);
    vq_hi_kernel<<<dim3(512, 4, 2), HTHR, smH>>>(                           // 4
        enc, embed_hi, label, out + Q_OFF);

    proj_kernel<<<512, NTHR, smP>>>(dec, org, W, bvec, label, out, out + PRED_OFF);  // 5

    final_k<<<1, 1>>>(out);                                                 // 6
}